// round 8
// baseline (speedup 1.0000x reference)
#include <cuda_runtime.h>
#include <math.h>

#define BB 4
#define SS 2048
#define DD 1024
#define BD (BB*DD)          // 4096
#define MT (BB*SS)          // 8192
#define CH 128
#define NC (SS/CH)          // 16

#define RP   128            // persistent CTAs in recurrence
#define RR   (DD/RP)        // 8 rows per CTA

typedef unsigned long long ull;

// ------------------------- scratch (device globals; no allocation) ---------
__device__ float g_ret[(size_t)MT*DD];
__device__ float g_inp[(size_t)MT*DD];
__device__ float g_gl [(size_t)MT*DD];
__device__ float g_ct [(size_t)MT*DD];
__device__ float g_st [(size_t)MT*DD];
__device__ float g_chend[BD*NC];
__device__ float g_carry[BD*NC];
__device__ float g_blend[2*BD];
__device__ __align__(16) unsigned g_flags[RP];

// ------------------------- helpers ------------------------------------------
__device__ __forceinline__ void cp_async16(unsigned dst, const void* src) {
    asm volatile("cp.async.cg.shared.global [%0], [%1], 16;" :: "r"(dst), "l"(src));
}
#define CP_COMMIT() asm volatile("cp.async.commit_group;")
#define CP_WAIT1()  asm volatile("cp.async.wait_group 1;")
#define CP_WAIT0()  asm volatile("cp.async.wait_group 0;")

__device__ __forceinline__ unsigned f2tf32(float x) {
    unsigned u; asm("cvt.rna.tf32.f32 %0, %1;" : "=r"(u) : "f"(x)); return u;
}
__device__ __forceinline__ void mma_tf32(float* c, const unsigned* a, const unsigned* b) {
    asm volatile(
        "mma.sync.aligned.m16n8k8.row.col.f32.tf32.tf32.f32 "
        "{%0,%1,%2,%3}, {%4,%5,%6,%7}, {%8,%9}, {%0,%1,%2,%3};"
        : "+f"(c[0]), "+f"(c[1]), "+f"(c[2]), "+f"(c[3])
        : "r"(a[0]), "r"(a[1]), "r"(a[2]), "r"(a[3]), "r"(b[0]), "r"(b[1]));
}
__device__ __forceinline__ void ffma2(ull& d, ull a, ull b) {
    asm volatile("fma.rn.f32x2 %0, %1, %2, %0;" : "+l"(d) : "l"(a), "l"(b));
}
__device__ __forceinline__ float2 unpack2(ull v) {
    float2 f; asm("mov.b64 {%0, %1}, %2;" : "=f"(f.x), "=f"(f.y) : "l"(v)); return f;
}
__device__ __forceinline__ float fsigmoid(float x) {
    return __fdividef(1.f, 1.f + __expf(-x));
}
__device__ __forceinline__ float ftanh(float x) {
    x = fminf(fmaxf(x, -15.f), 15.f);
    float e = __expf(2.f * x);
    return __fdividef(e - 1.f, e + 1.f);
}
__device__ __forceinline__ uint4 ld_flag4(const unsigned* p) {
    uint4 r;
    asm volatile("ld.global.cg.v4.u32 {%0,%1,%2,%3}, [%4];"
                 : "=r"(r.x), "=r"(r.y), "=r"(r.z), "=r"(r.w) : "l"(p) : "memory");
    return r;
}
__device__ __forceinline__ void st_flag(unsigned* p, unsigned v) {
    asm volatile("st.global.cg.u32 [%0], %1;" :: "l"(p), "r"(v) : "memory");
}

// ------------------------- misc ---------------------------------------------
__global__ void k_reset() { if (threadIdx.x < RP) g_flags[threadIdx.x] = 0u; }

// ------------------------- retention scan (chunked parallel scan) ----------
__global__ void k_scan1(const float* __restrict__ k, const float* __restrict__ v,
                        const float* __restrict__ decay)
{
    int g = blockIdx.x * blockDim.x + threadIdx.x;
    int d    = g & (DD-1);
    int rest = g >> 10;
    int ch   = rest & (NC-1);
    int b    = rest >> 4;
    float dec = decay[d >> 6];
    size_t base = ((size_t)(b*SS + ch*CH))*DD + d;
    float r = 0.f;
#pragma unroll 4
    for (int t = 0; t < CH; t++) {
        r = dec*r + k[base + (size_t)t*DD] * v[base + (size_t)t*DD];
    }
    g_chend[(b*NC + ch)*DD + d] = r;
}

__global__ void k_scan2(const float* __restrict__ decay)
{
    int g = blockIdx.x * blockDim.x + threadIdx.x;
    int d = g & (DD-1);
    int b = g >> 10;
    float dec = decay[d >> 6];
    float dL = dec;
#pragma unroll
    for (int i = 0; i < 7; i++) dL *= dL;   // dec^128
    float r = 0.f;
#pragma unroll
    for (int ch = 0; ch < NC; ch++) {
        g_carry[(b*NC + ch)*DD + d] = r;
        r = g_chend[(b*NC + ch)*DD + d] + dL * r;
    }
}

__global__ void k_scan3(const float* __restrict__ q, const float* __restrict__ k,
                        const float* __restrict__ v, const float* __restrict__ decay)
{
    int g = blockIdx.x * blockDim.x + threadIdx.x;
    int d    = g & (DD-1);
    int rest = g >> 10;
    int ch   = rest & (NC-1);
    int b    = rest >> 4;
    float dec = decay[d >> 6];
    float r = g_carry[(b*NC + ch)*DD + d];
    size_t base = ((size_t)(b*SS + ch*CH))*DD + d;
#pragma unroll 4
    for (int t = 0; t < CH; t++) {
        size_t o = base + (size_t)t*DD;
        r = dec*r + k[o]*v[o];
        g_ret[o] = q[o]*r;
    }
}

// ------------------------- TF32-split tensor-core GEMM (frozen, R4) ---------
#define GBK  16
#define GSTR 20

__global__ __launch_bounds__(256)
void k_gemm(const float* __restrict__ Act, const float* __restrict__ W,
            const float* __restrict__ bias, float* __restrict__ C,
            int M, int N, int K, int hasBias)
{
    __shared__ float As[2][128*GSTR];
    __shared__ float Bs[2][128*GSTR];
    int tid  = threadIdx.x;
    int wid  = tid >> 5;
    int lane = tid & 31;
    int g    = lane >> 2;
    int tig  = lane & 3;
    int wm   = wid & 3;
    int wn   = wid >> 2;

    const float* Ab = Act + (size_t)blockIdx.y * 128 * K;
    const float* Wb = W   + (size_t)blockIdx.x * 128 * K;
    unsigned sA0 = (unsigned)__cvta_generic_to_shared(&As[0][0]);
    unsigned sB0 = (unsigned)__cvta_generic_to_shared(&Bs[0][0]);

    float acc[2][8][4];
#pragma unroll
    for (int mt = 0; mt < 2; mt++)
#pragma unroll
        for (int nt = 0; nt < 8; nt++)
#pragma unroll
            for (int i = 0; i < 4; i++) acc[mt][nt][i] = 0.f;

    auto loadTile = [&](int buf, int k0) {
        int f = tid * 2;
#pragma unroll
        for (int i2 = 0; i2 < 2; i2++) {
            int ff  = f + i2;
            int row = ff >> 2;
            int c4  = (ff & 3) * 4;
            cp_async16(sA0 + (unsigned)(buf*128*GSTR + row*GSTR + c4)*4u,
                       Ab + (size_t)row*K + k0 + c4);
            cp_async16(sB0 + (unsigned)(buf*128*GSTR + row*GSTR + c4)*4u,
                       Wb + (size_t)row*K + k0 + c4);
        }
    };

    int nk = K / GBK;
    loadTile(0, 0);
    CP_COMMIT();

    for (int kt = 0; kt < nk; kt++) {
        if (kt + 1 < nk) { loadTile((kt+1) & 1, (kt+1)*GBK); CP_COMMIT(); CP_WAIT1(); }
        else             { CP_WAIT0(); }
        __syncthreads();

        const float* Abs = &As[kt & 1][0];
        const float* Bbs = &Bs[kt & 1][0];
#pragma unroll
        for (int ks = 0; ks < GBK/8; ks++) {
            int kb = ks*8;
            unsigned ah[2][4], al[2][4];
#pragma unroll
            for (int mt = 0; mt < 2; mt++) {
                int rb = wm*32 + mt*16;
                float f0 = Abs[(rb + g    )*GSTR + kb + tig    ];
                float f1 = Abs[(rb + g + 8)*GSTR + kb + tig    ];
                float f2 = Abs[(rb + g    )*GSTR + kb + tig + 4];
                float f3 = Abs[(rb + g + 8)*GSTR + kb + tig + 4];
                ah[mt][0] = f2tf32(f0); al[mt][0] = f2tf32(f0 - __uint_as_float(ah[mt][0]));
                ah[mt][1] = f2tf32(f1); al[mt][1] = f2tf32(f1 - __uint_as_float(ah[mt][1]));
                ah[mt][2] = f2tf32(f2); al[mt][2] = f2tf32(f2 - __uint_as_float(ah[mt][2]));
                ah[mt][3] = f2tf32(f3); al[mt][3] = f2tf32(f3 - __uint_as_float(ah[mt][3]));
            }
            unsigned bh[8][2], bl[8][2];
#pragma unroll
            for (int nt = 0; nt < 8; nt++) {
                int nb = wn*64 + nt*8;
                float f0 = Bbs[(nb + g)*GSTR + kb + tig    ];
                float f1 = Bbs[(nb + g)*GSTR + kb + tig + 4];
                bh[nt][0] = f2tf32(f0); bl[nt][0] = f2tf32(f0 - __uint_as_float(bh[nt][0]));
                bh[nt][1] = f2tf32(f1); bl[nt][1] = f2tf32(f1 - __uint_as_float(bh[nt][1]));
            }
#pragma unroll
            for (int mt = 0; mt < 2; mt++)
#pragma unroll
                for (int nt = 0; nt < 8; nt++) {
                    mma_tf32(acc[mt][nt], ah[mt], bh[nt]);
                    mma_tf32(acc[mt][nt], ah[mt], bl[nt]);
                    mma_tf32(acc[mt][nt], al[mt], bh[nt]);
                }
        }
        __syncthreads();
    }

#pragma unroll
    for (int mt = 0; mt < 2; mt++) {
        int r0 = blockIdx.y*128 + wm*32 + mt*16 + g;
#pragma unroll
        for (int nt = 0; nt < 8; nt++) {
            int c0 = blockIdx.x*128 + wn*64 + nt*8 + 2*tig;
            float b0 = hasBias ? bias[c0]     : 0.f;
            float b1 = hasBias ? bias[c0 + 1] : 0.f;
            float2 o0 = make_float2(acc[mt][nt][0] + b0, acc[mt][nt][1] + b1);
            float2 o1 = make_float2(acc[mt][nt][2] + b0, acc[mt][nt][3] + b1);
            *(float2*)(C + (size_t)r0      *N + c0) = o0;
            *(float2*)(C + (size_t)(r0 + 8)*N + c0) = o1;
        }
    }
}

// ------------------------- sequential state recurrence ----------------------
// R5 structure (single polling warp + syncA — proven safe), but arrival is a
// plain release store to a PER-CTA flag (distinct addresses: no LTS atomic-ALU
// serialization). Warp 0 polls all 128 flags with one LDG.128 per lane and
// nanosleep backoff (no LSU flooding, unlike R6).
__global__ __launch_bounds__(256, 1)
void k_recur(const float* __restrict__ Amat)
{
    __shared__ float bl_s[4][1032];   // padded: conflict-free GEMV broadcast
    __shared__ float part[8][32];

    int tid  = threadIdx.x;
    int cta  = blockIdx.x;
    int row0 = cta * RR;
    int w    = tid >> 5;              // warp = k-chunk of 128
    int lane = tid & 31;
    int lr   = lane >> 2;             // local row 0..7
    int bo   = lane & 3;              // batch 0..3

    // A slice in registers, k-pair packed: A[row0+lr][w*128 .. +127]
    ull a2[64];
    {
        const ulonglong2* Ar =
            (const ulonglong2*)(Amat + (size_t)(row0 + lr)*DD + w*128);
#pragma unroll
        for (int i = 0; i < 32; i++) {
            ulonglong2 u = Ar[i];
            a2[2*i]   = u.x;
            a2[2*i+1] = u.y;
        }
    }

    int b2 = tid & 3, l2 = tid >> 2;          // meaningful for tid<32
    size_t idx0 = ((size_t)b2*SS)*DD + row0 + l2;
    float state = 0.f;
    float pf_gl = 0.f, pf_inp = 0.f, pf_ct = 0.f;
    if (tid < 32) {
        pf_gl  = g_gl [idx0];
        pf_inp = g_inp[idx0];
        pf_ct  = g_ct [idx0];
    }
    __syncthreads();

    const unsigned* myflags = &g_flags[lane * 4];   // lane L watches flags 4L..4L+3

    for (int t = 0; t < SS; t++) {
        // 1) warp 0: blend + publish + release flag; prefetch t+1; poll.
        if (tid < 32) {
            float gate = fsigmoid(pf_gl);
            float bl = fmaf(gate, state - pf_inp, pf_inp);
            __stcg(&g_blend[(t & 1)*BD + b2*DD + row0 + l2], bl);
            __syncwarp();
            if (tid == 0) {
                __threadfence();                   // order publish before flag
                st_flag(&g_flags[cta], (unsigned)(t + 1));
            }
            // prefetch next step's gate logits / inp (hidden by barrier+GEMV)
            int tn = (t + 1 < SS) ? t + 1 : t;
            size_t nidx = idx0 + (size_t)tn*DD;
            pf_gl  = g_gl [nidx];
            pf_inp = g_inp[nidx];

            // wait: warp 0 only, vectorized flag read + backoff
            unsigned tgt = (unsigned)(t + 1);
            for (;;) {
                uint4 f = ld_flag4(myflags);
                bool ok = (f.x >= tgt) & (f.y >= tgt) & (f.z >= tgt) & (f.w >= tgt);
                if (__all_sync(0xffffffffu, ok)) break;
                __nanosleep(32);
            }
            __threadfence();                       // acquire half
        }
        __syncthreads();   // syncA: barrier passed

        // 2) stage full blended vector into SMEM (L1-bypassed)
        {
            const float4* src = (const float4*)(g_blend + (t & 1)*BD);
#pragma unroll
            for (int i = 0; i < 4; i++) {
                int idx = tid + i*256;            // 1024 float4
                float4 vv = __ldcg(src + idx);
                int bb = idx >> 8;
                int k4 = (idx & 255) * 4;
                *(float4*)&bl_s[bb][k4] = vv;
            }
        }
        __syncthreads();   // syncB: tile staged

        // 3) register-A GEMV over this warp's k-chunk (packed f32x2)
        {
            const ulonglong2* xb = (const ulonglong2*)&bl_s[bo][w*128];
            ull s0 = 0ull, s1 = 0ull;
#pragma unroll
            for (int i = 0; i < 32; i++) {
                ulonglong2 x = xb[i];
                ffma2(s0, a2[2*i],   x.x);
                ffma2(s1, a2[2*i+1], x.y);
            }
            float2 p0 = unpack2(s0), p1 = unpack2(s1);
            part[w][lane] = (p0.x + p0.y) + (p1.x + p1.y);
        }
        __syncthreads();   // syncC: partials ready

        // 4) warp 0: reduce, add Bm-term, tanh, commit; prefetch next ct.
        //    (No trailing sync: other warps wait at syncA of t+1.)
        if (tid < 32) {
            float s = pf_ct;
#pragma unroll
            for (int ww = 0; ww < 8; ww++) s += part[ww][tid];
            state = ftanh(s);
            __stcg(&g_st[idx0 + (size_t)t*DD], state);
            int tn = (t + 1 < SS) ? t + 1 : t;
            pf_ct = g_ct[idx0 + (size_t)tn*DD];
        }
    }
}

// ------------------------- launch -------------------------------------------
extern "C" void kernel_launch(void* const* d_in, const int* in_sizes, int n_in,
                              void* d_out, int out_size)
{
    const float* q     = (const float*)d_in[0];
    const float* k     = (const float*)d_in[1];
    const float* v     = (const float*)d_in[2];
    const float* Wi    = (const float*)d_in[3];
    const float* bi    = (const float*)d_in[4];
    const float* Wg    = (const float*)d_in[5];
    const float* bg    = (const float*)d_in[6];
    const float* A     = (const float*)d_in[7];
    const float* Bm    = (const float*)d_in[8];
    const float* Wo    = (const float*)d_in[9];
    const float* bo    = (const float*)d_in[10];
    const float* decay = (const float*)d_in[11];
    float* out = (float*)d_out;

    void *p_ret, *p_inp, *p_gl, *p_ct, *p_st;
    cudaGetSymbolAddress(&p_ret, g_ret);
    cudaGetSymbolAddress(&p_inp, g_inp);
    cudaGetSymbolAddress(&p_gl,  g_gl);
    cudaGetSymbolAddress(&p_ct,  g_ct);
    cudaGetSymbolAddress(&p_st,  g_st);

    k_reset<<<1, 128>>>();

    k_scan1<<<(BD*NC)/256, 256>>>(k, v, decay);
    k_scan2<<<BD/256, 256>>>(decay);
    k_scan3<<<(BD*NC)/256, 256>>>(q, k, v, decay);

    dim3 gg(DD/128, MT/128);   // (N tiles, M tiles)
    k_gemm<<<gg, 256>>>((const float*)p_ret, Wi, bi, (float*)p_inp, MT, DD, DD, 1);
    k_gemm<<<gg, 256>>>((const float*)p_inp, Wg, bg, (float*)p_gl, MT, DD, DD, 1);
    k_gemm<<<gg, 256>>>((const float*)p_inp, Bm, (const float*)0, (float*)p_ct, MT, DD, DD, 0);

    k_recur<<<RP, 256>>>(A);

    k_gemm<<<gg, 256>>>((const float*)p_st, Wo, bo, out, MT, DD, DD, 1);
}

// round 9
// speedup vs baseline: 2.8225x; 2.8225x over previous
#include <cuda_runtime.h>
#include <math.h>

#define BB 4
#define SS 2048
#define DD 1024
#define BD (BB*DD)          // 4096
#define MT (BB*SS)          // 8192
#define CH 128
#define NC (SS/CH)          // 16

#define RP   128            // persistent CTAs in recurrence
#define RR   (DD/RP)        // 8 rows per CTA

typedef unsigned long long ull;

// ------------------------- scratch (device globals; no allocation) ---------
__device__ float g_ret[(size_t)MT*DD];
__device__ float g_inp[(size_t)MT*DD];
__device__ float g_gl [(size_t)MT*DD];
__device__ float g_ct [(size_t)MT*DD];
__device__ float g_st [(size_t)MT*DD];
__device__ float g_chend[BD*NC];
__device__ float g_carry[BD*NC];
__device__ float g_blend[2*BD];
__device__ unsigned g_bar;

// ------------------------- helpers ------------------------------------------
__device__ __forceinline__ void cp_async16(unsigned dst, const void* src) {
    asm volatile("cp.async.cg.shared.global [%0], [%1], 16;" :: "r"(dst), "l"(src));
}
#define CP_COMMIT() asm volatile("cp.async.commit_group;")
#define CP_WAIT1()  asm volatile("cp.async.wait_group 1;")
#define CP_WAIT0()  asm volatile("cp.async.wait_group 0;")

__device__ __forceinline__ unsigned f2tf32(float x) {
    unsigned u; asm("cvt.rna.tf32.f32 %0, %1;" : "=r"(u) : "f"(x)); return u;
}
__device__ __forceinline__ void mma_tf32(float* c, const unsigned* a, const unsigned* b) {
    asm volatile(
        "mma.sync.aligned.m16n8k8.row.col.f32.tf32.tf32.f32 "
        "{%0,%1,%2,%3}, {%4,%5,%6,%7}, {%8,%9}, {%0,%1,%2,%3};"
        : "+f"(c[0]), "+f"(c[1]), "+f"(c[2]), "+f"(c[3])
        : "r"(a[0]), "r"(a[1]), "r"(a[2]), "r"(a[3]), "r"(b[0]), "r"(b[1]));
}
__device__ __forceinline__ void ffma2(ull& d, ull a, ull b) {
    asm volatile("fma.rn.f32x2 %0, %1, %2, %0;" : "+l"(d) : "l"(a), "l"(b));
}
__device__ __forceinline__ float2 unpack2(ull v) {
    float2 f; asm("mov.b64 {%0, %1}, %2;" : "=f"(f.x), "=f"(f.y) : "l"(v)); return f;
}
__device__ __forceinline__ float fsigmoid(float x) {
    return __fdividef(1.f, 1.f + __expf(-x));
}
__device__ __forceinline__ float ftanh(float x) {
    x = fminf(fmaxf(x, -15.f), 15.f);
    float e = __expf(2.f * x);
    return __fdividef(e - 1.f, e + 1.f);
}

// ------------------------- misc ---------------------------------------------
__global__ void k_reset() { g_bar = 0u; }

// ------------------------- retention scan (chunked parallel scan) ----------
__global__ void k_scan1(const float* __restrict__ k, const float* __restrict__ v,
                        const float* __restrict__ decay)
{
    int g = blockIdx.x * blockDim.x + threadIdx.x;
    int d    = g & (DD-1);
    int rest = g >> 10;
    int ch   = rest & (NC-1);
    int b    = rest >> 4;
    float dec = decay[d >> 6];
    size_t base = ((size_t)(b*SS + ch*CH))*DD + d;
    float r = 0.f;
#pragma unroll 4
    for (int t = 0; t < CH; t++) {
        r = dec*r + k[base + (size_t)t*DD] * v[base + (size_t)t*DD];
    }
    g_chend[(b*NC + ch)*DD + d] = r;
}

__global__ void k_scan2(const float* __restrict__ decay)
{
    int g = blockIdx.x * blockDim.x + threadIdx.x;
    int d = g & (DD-1);
    int b = g >> 10;
    float dec = decay[d >> 6];
    float dL = dec;
#pragma unroll
    for (int i = 0; i < 7; i++) dL *= dL;   // dec^128
    float r = 0.f;
#pragma unroll
    for (int ch = 0; ch < NC; ch++) {
        g_carry[(b*NC + ch)*DD + d] = r;
        r = g_chend[(b*NC + ch)*DD + d] + dL * r;
    }
}

__global__ void k_scan3(const float* __restrict__ q, const float* __restrict__ k,
                        const float* __restrict__ v, const float* __restrict__ decay)
{
    int g = blockIdx.x * blockDim.x + threadIdx.x;
    int d    = g & (DD-1);
    int rest = g >> 10;
    int ch   = rest & (NC-1);
    int b    = rest >> 4;
    float dec = decay[d >> 6];
    float r = g_carry[(b*NC + ch)*DD + d];
    size_t base = ((size_t)(b*SS + ch*CH))*DD + d;
#pragma unroll 4
    for (int t = 0; t < CH; t++) {
        size_t o = base + (size_t)t*DD;
        r = dec*r + k[o]*v[o];
        g_ret[o] = q[o]*r;
    }
}

// ------------------------- TF32-split tensor-core GEMM (frozen, R4) ---------
#define GBK  16
#define GSTR 20

__global__ __launch_bounds__(256)
void k_gemm(const float* __restrict__ Act, const float* __restrict__ W,
            const float* __restrict__ bias, float* __restrict__ C,
            int M, int N, int K, int hasBias)
{
    __shared__ float As[2][128*GSTR];
    __shared__ float Bs[2][128*GSTR];
    int tid  = threadIdx.x;
    int wid  = tid >> 5;
    int lane = tid & 31;
    int g    = lane >> 2;
    int tig  = lane & 3;
    int wm   = wid & 3;
    int wn   = wid >> 2;

    const float* Ab = Act + (size_t)blockIdx.y * 128 * K;
    const float* Wb = W   + (size_t)blockIdx.x * 128 * K;
    unsigned sA0 = (unsigned)__cvta_generic_to_shared(&As[0][0]);
    unsigned sB0 = (unsigned)__cvta_generic_to_shared(&Bs[0][0]);

    float acc[2][8][4];
#pragma unroll
    for (int mt = 0; mt < 2; mt++)
#pragma unroll
        for (int nt = 0; nt < 8; nt++)
#pragma unroll
            for (int i = 0; i < 4; i++) acc[mt][nt][i] = 0.f;

    auto loadTile = [&](int buf, int k0) {
        int f = tid * 2;
#pragma unroll
        for (int i2 = 0; i2 < 2; i2++) {
            int ff  = f + i2;
            int row = ff >> 2;
            int c4  = (ff & 3) * 4;
            cp_async16(sA0 + (unsigned)(buf*128*GSTR + row*GSTR + c4)*4u,
                       Ab + (size_t)row*K + k0 + c4);
            cp_async16(sB0 + (unsigned)(buf*128*GSTR + row*GSTR + c4)*4u,
                       Wb + (size_t)row*K + k0 + c4);
        }
    };

    int nk = K / GBK;
    loadTile(0, 0);
    CP_COMMIT();

    for (int kt = 0; kt < nk; kt++) {
        if (kt + 1 < nk) { loadTile((kt+1) & 1, (kt+1)*GBK); CP_COMMIT(); CP_WAIT1(); }
        else             { CP_WAIT0(); }
        __syncthreads();

        const float* Abs = &As[kt & 1][0];
        const float* Bbs = &Bs[kt & 1][0];
#pragma unroll
        for (int ks = 0; ks < GBK/8; ks++) {
            int kb = ks*8;
            unsigned ah[2][4], al[2][4];
#pragma unroll
            for (int mt = 0; mt < 2; mt++) {
                int rb = wm*32 + mt*16;
                float f0 = Abs[(rb + g    )*GSTR + kb + tig    ];
                float f1 = Abs[(rb + g + 8)*GSTR + kb + tig    ];
                float f2 = Abs[(rb + g    )*GSTR + kb + tig + 4];
                float f3 = Abs[(rb + g + 8)*GSTR + kb + tig + 4];
                ah[mt][0] = f2tf32(f0); al[mt][0] = f2tf32(f0 - __uint_as_float(ah[mt][0]));
                ah[mt][1] = f2tf32(f1); al[mt][1] = f2tf32(f1 - __uint_as_float(ah[mt][1]));
                ah[mt][2] = f2tf32(f2); al[mt][2] = f2tf32(f2 - __uint_as_float(ah[mt][2]));
                ah[mt][3] = f2tf32(f3); al[mt][3] = f2tf32(f3 - __uint_as_float(ah[mt][3]));
            }
            unsigned bh[8][2], bl[8][2];
#pragma unroll
            for (int nt = 0; nt < 8; nt++) {
                int nb = wn*64 + nt*8;
                float f0 = Bbs[(nb + g)*GSTR + kb + tig    ];
                float f1 = Bbs[(nb + g)*GSTR + kb + tig + 4];
                bh[nt][0] = f2tf32(f0); bl[nt][0] = f2tf32(f0 - __uint_as_float(bh[nt][0]));
                bh[nt][1] = f2tf32(f1); bl[nt][1] = f2tf32(f1 - __uint_as_float(bh[nt][1]));
            }
#pragma unroll
            for (int mt = 0; mt < 2; mt++)
#pragma unroll
                for (int nt = 0; nt < 8; nt++) {
                    mma_tf32(acc[mt][nt], ah[mt], bh[nt]);
                    mma_tf32(acc[mt][nt], ah[mt], bl[nt]);
                    mma_tf32(acc[mt][nt], al[mt], bh[nt]);
                }
        }
        __syncthreads();
    }

#pragma unroll
    for (int mt = 0; mt < 2; mt++) {
        int r0 = blockIdx.y*128 + wm*32 + mt*16 + g;
#pragma unroll
        for (int nt = 0; nt < 8; nt++) {
            int c0 = blockIdx.x*128 + wn*64 + nt*8 + 2*tig;
            float b0 = hasBias ? bias[c0]     : 0.f;
            float b1 = hasBias ? bias[c0 + 1] : 0.f;
            float2 o0 = make_float2(acc[mt][nt][0] + b0, acc[mt][nt][1] + b1);
            float2 o1 = make_float2(acc[mt][nt][2] + b0, acc[mt][nt][3] + b1);
            *(float2*)(C + (size_t)r0      *N + c0) = o0;
            *(float2*)(C + (size_t)(r0 + 8)*N + c0) = o1;
        }
    }
}

// ------------------------- sequential state recurrence ----------------------
// R5 structure with the PROVEN atomic-counter barrier (frozen verbatim).
// Trims: per-warp self-staging (drops syncB), gate hoisted off the serial
// tail, ct cur/next register rotation.
__global__ __launch_bounds__(256, 1)
void k_recur(const float* __restrict__ Amat)
{
    __shared__ float bl_sw[8][4][132];   // per-warp slice: [warp][batch][128+pad]
    __shared__ float part[8][32];

    int tid  = threadIdx.x;
    int cta  = blockIdx.x;
    int row0 = cta * RR;
    int w    = tid >> 5;              // warp = k-chunk of 128
    int lane = tid & 31;
    int lr   = lane >> 2;             // local row 0..7
    int bo   = lane & 3;              // batch 0..3

    // A slice in registers, k-pair packed: A[row0+lr][w*128 .. +127]
    ull a2[64];
    {
        const ulonglong2* Ar =
            (const ulonglong2*)(Amat + (size_t)(row0 + lr)*DD + w*128);
#pragma unroll
        for (int i = 0; i < 32; i++) {
            ulonglong2 u = Ar[i];
            a2[2*i]   = u.x;
            a2[2*i+1] = u.y;
        }
    }

    int b2 = tid & 3, l2 = tid >> 2;          // meaningful for tid<32
    size_t idx0 = ((size_t)b2*SS)*DD + row0 + l2;
    float state = 0.f, gate = 0.f;
    float pf_gl = 0.f, pf_inp = 0.f, ct_cur = 0.f;
    if (tid < 32) {
        pf_gl  = g_gl [idx0];
        pf_inp = g_inp[idx0];
        ct_cur = g_ct [idx0];
        gate   = fsigmoid(pf_gl);
    }
    __syncthreads();

    for (int t = 0; t < SS; t++) {
        float ct_next = ct_cur;
        // 1) warp 0: blend + publish + arrive; prefetch t+1; poll; gate(t+1)
        if (tid < 32) {
            float bl = fmaf(gate, state - pf_inp, pf_inp);
            __stcg(&g_blend[(t & 1)*BD + b2*DD + row0 + l2], bl);
            __syncwarp();
            if (tid == 0) {
                __threadfence();
                atomicAdd(&g_bar, 1u);
            }
            int tn = (t + 1 < SS) ? t + 1 : t;
            size_t nidx = idx0 + (size_t)tn*DD;
            pf_gl   = g_gl [nidx];
            pf_inp  = g_inp[nidx];
            ct_next = g_ct [nidx];
            if (tid == 0) {
                unsigned target = (unsigned)(t + 1) * RP;
                while (*(volatile unsigned*)&g_bar < target) { __nanosleep(32); }
                __threadfence();
            }
            __syncwarp();
            gate = fsigmoid(pf_gl);        // off the serial tail
        }
        __syncthreads();   // syncA: barrier passed, blend[t] visible

        // 2) per-warp self-stage: this warp's 2KB slice (4 batches x 128 floats)
        {
            const float4* src = (const float4*)(g_blend + (t & 1)*BD);
#pragma unroll
            for (int i = 0; i < 4; i++) {
                float4 vv = __ldcg(src + (size_t)i*(DD/4) + w*32 + lane);
                *(float4*)&bl_sw[w][i][lane*4] = vv;
            }
            __syncwarp();
        }

        // 3) register-A GEMV over this warp's k-chunk (packed f32x2)
        {
            const ulonglong2* xb = (const ulonglong2*)&bl_sw[w][bo][0];
            ull s0 = 0ull, s1 = 0ull;
#pragma unroll
            for (int i = 0; i < 32; i++) {
                ulonglong2 x = xb[i];
                ffma2(s0, a2[2*i],   x.x);
                ffma2(s1, a2[2*i+1], x.y);
            }
            float2 p0 = unpack2(s0), p1 = unpack2(s1);
            part[w][lane] = (p0.x + p0.y) + (p1.x + p1.y);
        }
        __syncthreads();   // syncC: partials ready

        // 4) warp 0: reduce + tanh + commit state (no trailing sync)
        if (tid < 32) {
            float s = ct_cur;
#pragma unroll
            for (int ww = 0; ww < 8; ww++) s += part[ww][tid];
            state = ftanh(s);
            __stcg(&g_st[idx0 + (size_t)t*DD], state);
            ct_cur = ct_next;
        }
    }
}

// ------------------------- launch -------------------------------------------
extern "C" void kernel_launch(void* const* d_in, const int* in_sizes, int n_in,
                              void* d_out, int out_size)
{
    const float* q     = (const float*)d_in[0];
    const float* k     = (const float*)d_in[1];
    const float* v     = (const float*)d_in[2];
    const float* Wi    = (const float*)d_in[3];
    const float* bi    = (const float*)d_in[4];
    const float* Wg    = (const float*)d_in[5];
    const float* bg    = (const float*)d_in[6];
    const float* A     = (const float*)d_in[7];
    const float* Bm    = (const float*)d_in[8];
    const float* Wo    = (const float*)d_in[9];
    const float* bo    = (const float*)d_in[10];
    const float* decay = (const float*)d_in[11];
    float* out = (float*)d_out;

    void *p_ret, *p_inp, *p_gl, *p_ct, *p_st;
    cudaGetSymbolAddress(&p_ret, g_ret);
    cudaGetSymbolAddress(&p_inp, g_inp);
    cudaGetSymbolAddress(&p_gl,  g_gl);
    cudaGetSymbolAddress(&p_ct,  g_ct);
    cudaGetSymbolAddress(&p_st,  g_st);

    k_reset<<<1, 1>>>();

    k_scan1<<<(BD*NC)/256, 256>>>(k, v, decay);
    k_scan2<<<BD/256, 256>>>(decay);
    k_scan3<<<(BD*NC)/256, 256>>>(q, k, v, decay);

    dim3 gg(DD/128, MT/128);   // (N tiles, M tiles)
    k_gemm<<<gg, 256>>>((const float*)p_ret, Wi, bi, (float*)p_inp, MT, DD, DD, 1);
    k_gemm<<<gg, 256>>>((const float*)p_inp, Wg, bg, (float*)p_gl, MT, DD, DD, 1);
    k_gemm<<<gg, 256>>>((const float*)p_inp, Bm, (const float*)0, (float*)p_ct, MT, DD, DD, 0);

    k_recur<<<RP, 256>>>(A);

    k_gemm<<<gg, 256>>>((const float*)p_st, Wo, bo, out, MT, DD, DD, 1);
}

// round 12
// speedup vs baseline: 2.8793x; 1.0201x over previous
#include <cuda_runtime.h>
#include <math.h>

#define BB 4
#define SS 2048
#define DD 1024
#define BD (BB*DD)          // 4096
#define MT (BB*SS)          // 8192
#define CH 128
#define NC (SS/CH)          // 16

#define RP   128            // persistent CTAs in recurrence
#define RR   (DD/RP)        // 8 rows per CTA

typedef unsigned long long ull;

// ------------------------- scratch (device globals; no allocation) ---------
__device__ float g_ret[(size_t)MT*DD];
__device__ float g_inp[(size_t)MT*DD];
__device__ float g_gl [(size_t)MT*DD];
__device__ float g_ct [(size_t)MT*DD];
__device__ float g_st [(size_t)MT*DD];
__device__ float g_chend[BD*NC];
__device__ float g_carry[BD*NC];
__device__ float g_blend[2*BD];
__device__ unsigned g_bar;

// ------------------------- helpers ------------------------------------------
__device__ __forceinline__ void cp_async16(unsigned dst, const void* src) {
    asm volatile("cp.async.cg.shared.global [%0], [%1], 16;" :: "r"(dst), "l"(src));
}
#define CP_COMMIT() asm volatile("cp.async.commit_group;")
#define CP_WAIT1()  asm volatile("cp.async.wait_group 1;")
#define CP_WAIT0()  asm volatile("cp.async.wait_group 0;")

__device__ __forceinline__ unsigned f2tf32(float x) {
    unsigned u; asm("cvt.rna.tf32.f32 %0, %1;" : "=r"(u) : "f"(x)); return u;
}
__device__ __forceinline__ void mma_tf32(float* c, const unsigned* a, const unsigned* b) {
    asm volatile(
        "mma.sync.aligned.m16n8k8.row.col.f32.tf32.tf32.f32 "
        "{%0,%1,%2,%3}, {%4,%5,%6,%7}, {%8,%9}, {%0,%1,%2,%3};"
        : "+f"(c[0]), "+f"(c[1]), "+f"(c[2]), "+f"(c[3])
        : "r"(a[0]), "r"(a[1]), "r"(a[2]), "r"(a[3]), "r"(b[0]), "r"(b[1]));
}
__device__ __forceinline__ void ffma2(ull& d, ull a, ull b) {
    asm volatile("fma.rn.f32x2 %0, %1, %2, %0;" : "+l"(d) : "l"(a), "l"(b));
}
__device__ __forceinline__ float2 unpack2(ull v) {
    float2 f; asm("mov.b64 {%0, %1}, %2;" : "=f"(f.x), "=f"(f.y) : "l"(v)); return f;
}
__device__ __forceinline__ float fsigmoid(float x) {
    return __fdividef(1.f, 1.f + __expf(-x));
}
__device__ __forceinline__ float ftanh(float x) {
    x = fminf(fmaxf(x, -15.f), 15.f);
    float e = __expf(2.f * x);
    return __fdividef(e - 1.f, e + 1.f);
}

// ------------------------- retention scan (chunked parallel scan) ----------
// k_reset fused here: shifts the harness's fixed ncu capture slot onto the
// first k_gemm launch (diagnostics), and saves one launch.
__global__ void k_scan1(const float* __restrict__ k, const float* __restrict__ v,
                        const float* __restrict__ decay)
{
    if (blockIdx.x == 0 && threadIdx.x == 0) g_bar = 0u;
    int g = blockIdx.x * blockDim.x + threadIdx.x;
    int d    = g & (DD-1);
    int rest = g >> 10;
    int ch   = rest & (NC-1);
    int b    = rest >> 4;
    float dec = decay[d >> 6];
    size_t base = ((size_t)(b*SS + ch*CH))*DD + d;
    float r = 0.f;
#pragma unroll 4
    for (int t = 0; t < CH; t++) {
        r = dec*r + k[base + (size_t)t*DD] * v[base + (size_t)t*DD];
    }
    g_chend[(b*NC + ch)*DD + d] = r;
}

__global__ void k_scan2(const float* __restrict__ decay)
{
    int g = blockIdx.x * blockDim.x + threadIdx.x;
    int d = g & (DD-1);
    int b = g >> 10;
    float dec = decay[d >> 6];
    float dL = dec;
#pragma unroll
    for (int i = 0; i < 7; i++) dL *= dL;   // dec^128
    float r = 0.f;
#pragma unroll
    for (int ch = 0; ch < NC; ch++) {
        g_carry[(b*NC + ch)*DD + d] = r;
        r = g_chend[(b*NC + ch)*DD + d] + dL * r;
    }
}

__global__ void k_scan3(const float* __restrict__ q, const float* __restrict__ k,
                        const float* __restrict__ v, const float* __restrict__ decay)
{
    int g = blockIdx.x * blockDim.x + threadIdx.x;
    int d    = g & (DD-1);
    int rest = g >> 10;
    int ch   = rest & (NC-1);
    int b    = rest >> 4;
    float dec = decay[d >> 6];
    float r = g_carry[(b*NC + ch)*DD + d];
    size_t base = ((size_t)(b*SS + ch*CH))*DD + d;
#pragma unroll 4
    for (int t = 0; t < CH; t++) {
        size_t o = base + (size_t)t*DD;
        r = dec*r + k[o]*v[o];
        g_ret[o] = q[o]*r;
    }
}

// ------------------------- TF32-split tensor-core GEMM (frozen, R4) ---------
#define GBK  16
#define GSTR 20

__global__ __launch_bounds__(256)
void k_gemm(const float* __restrict__ Act, const float* __restrict__ W,
            const float* __restrict__ bias, float* __restrict__ C,
            int M, int N, int K, int hasBias)
{
    __shared__ float As[2][128*GSTR];
    __shared__ float Bs[2][128*GSTR];
    int tid  = threadIdx.x;
    int wid  = tid >> 5;
    int lane = tid & 31;
    int g    = lane >> 2;
    int tig  = lane & 3;
    int wm   = wid & 3;
    int wn   = wid >> 2;

    const float* Ab = Act + (size_t)blockIdx.y * 128 * K;
    const float* Wb = W   + (size_t)blockIdx.x * 128 * K;
    unsigned sA0 = (unsigned)__cvta_generic_to_shared(&As[0][0]);
    unsigned sB0 = (unsigned)__cvta_generic_to_shared(&Bs[0][0]);

    float acc[2][8][4];
#pragma unroll
    for (int mt = 0; mt < 2; mt++)
#pragma unroll
        for (int nt = 0; nt < 8; nt++)
#pragma unroll
            for (int i = 0; i < 4; i++) acc[mt][nt][i] = 0.f;

    auto loadTile = [&](int buf, int k0) {
        int f = tid * 2;
#pragma unroll
        for (int i2 = 0; i2 < 2; i2++) {
            int ff  = f + i2;
            int row = ff >> 2;
            int c4  = (ff & 3) * 4;
            cp_async16(sA0 + (unsigned)(buf*128*GSTR + row*GSTR + c4)*4u,
                       Ab + (size_t)row*K + k0 + c4);
            cp_async16(sB0 + (unsigned)(buf*128*GSTR + row*GSTR + c4)*4u,
                       Wb + (size_t)row*K + k0 + c4);
        }
    };

    int nk = K / GBK;
    loadTile(0, 0);
    CP_COMMIT();

    for (int kt = 0; kt < nk; kt++) {
        if (kt + 1 < nk) { loadTile((kt+1) & 1, (kt+1)*GBK); CP_COMMIT(); CP_WAIT1(); }
        else             { CP_WAIT0(); }
        __syncthreads();

        const float* Abs = &As[kt & 1][0];
        const float* Bbs = &Bs[kt & 1][0];
#pragma unroll
        for (int ks = 0; ks < GBK/8; ks++) {
            int kb = ks*8;
            unsigned ah[2][4], al[2][4];
#pragma unroll
            for (int mt = 0; mt < 2; mt++) {
                int rb = wm*32 + mt*16;
                float f0 = Abs[(rb + g    )*GSTR + kb + tig    ];
                float f1 = Abs[(rb + g + 8)*GSTR + kb + tig    ];
                float f2 = Abs[(rb + g    )*GSTR + kb + tig + 4];
                float f3 = Abs[(rb + g + 8)*GSTR + kb + tig + 4];
                ah[mt][0] = f2tf32(f0); al[mt][0] = f2tf32(f0 - __uint_as_float(ah[mt][0]));
                ah[mt][1] = f2tf32(f1); al[mt][1] = f2tf32(f1 - __uint_as_float(ah[mt][1]));
                ah[mt][2] = f2tf32(f2); al[mt][2] = f2tf32(f2 - __uint_as_float(ah[mt][2]));
                ah[mt][3] = f2tf32(f3); al[mt][3] = f2tf32(f3 - __uint_as_float(ah[mt][3]));
            }
            unsigned bh[8][2], bl[8][2];
#pragma unroll
            for (int nt = 0; nt < 8; nt++) {
                int nb = wn*64 + nt*8;
                float f0 = Bbs[(nb + g)*GSTR + kb + tig    ];
                float f1 = Bbs[(nb + g)*GSTR + kb + tig + 4];
                bh[nt][0] = f2tf32(f0); bl[nt][0] = f2tf32(f0 - __uint_as_float(bh[nt][0]));
                bh[nt][1] = f2tf32(f1); bl[nt][1] = f2tf32(f1 - __uint_as_float(bh[nt][1]));
            }
#pragma unroll
            for (int mt = 0; mt < 2; mt++)
#pragma unroll
                for (int nt = 0; nt < 8; nt++) {
                    mma_tf32(acc[mt][nt], ah[mt], bh[nt]);
                    mma_tf32(acc[mt][nt], ah[mt], bl[nt]);
                    mma_tf32(acc[mt][nt], al[mt], bh[nt]);
                }
        }
        __syncthreads();
    }

#pragma unroll
    for (int mt = 0; mt < 2; mt++) {
        int r0 = blockIdx.y*128 + wm*32 + mt*16 + g;
#pragma unroll
        for (int nt = 0; nt < 8; nt++) {
            int c0 = blockIdx.x*128 + wn*64 + nt*8 + 2*tig;
            float b0 = hasBias ? bias[c0]     : 0.f;
            float b1 = hasBias ? bias[c0 + 1] : 0.f;
            float2 o0 = make_float2(acc[mt][nt][0] + b0, acc[mt][nt][1] + b1);
            float2 o1 = make_float2(acc[mt][nt][2] + b0, acc[mt][nt][3] + b1);
            *(float2*)(C + (size_t)r0      *N + c0) = o0;
            *(float2*)(C + (size_t)(r0 + 8)*N + c0) = o1;
        }
    }
}

// ------------------------- sequential state recurrence ----------------------
// R8 structure, single change: the barrier poller spins on a volatile load
// with NO __nanosleep (suspected coarse wakeup quantization was adding
// ~1-2us/step). Only 128 threads chip-wide poll one L2 line — benign.
__global__ __launch_bounds__(256, 1)
void k_recur(const float* __restrict__ Amat)
{
    __shared__ float bl_sw[8][4][132];   // per-warp slice: [warp][batch][128+pad]
    __shared__ float part[8][32];

    int tid  = threadIdx.x;
    int cta  = blockIdx.x;
    int row0 = cta * RR;
    int w    = tid >> 5;              // warp = k-chunk of 128
    int lane = tid & 31;
    int lr   = lane >> 2;             // local row 0..7
    int bo   = lane & 3;              // batch 0..3

    // A slice in registers, k-pair packed: A[row0+lr][w*128 .. +127]
    ull a2[64];
    {
        const ulonglong2* Ar =
            (const ulonglong2*)(Amat + (size_t)(row0 + lr)*DD + w*128);
#pragma unroll
        for (int i = 0; i < 32; i++) {
            ulonglong2 u = Ar[i];
            a2[2*i]   = u.x;
            a2[2*i+1] = u.y;
        }
    }

    int b2 = tid & 3, l2 = tid >> 2;          // meaningful for tid<32
    size_t idx0 = ((size_t)b2*SS)*DD + row0 + l2;
    float state = 0.f, gate = 0.f;
    float pf_gl = 0.f, pf_inp = 0.f, ct_cur = 0.f;
    if (tid < 32) {
        pf_gl  = g_gl [idx0];
        pf_inp = g_inp[idx0];
        ct_cur = g_ct [idx0];
        gate   = fsigmoid(pf_gl);
    }
    __syncthreads();

    for (int t = 0; t < SS; t++) {
        float ct_next = ct_cur;
        // 1) warp 0: blend + publish + arrive; prefetch t+1; spin-poll; gate(t+1)
        if (tid < 32) {
            float bl = fmaf(gate, state - pf_inp, pf_inp);
            __stcg(&g_blend[(t & 1)*BD + b2*DD + row0 + l2], bl);
            __syncwarp();
            if (tid == 0) {
                __threadfence();
                atomicAdd(&g_bar, 1u);
            }
            int tn = (t + 1 < SS) ? t + 1 : t;
            size_t nidx = idx0 + (size_t)tn*DD;
            pf_gl   = g_gl [nidx];
            pf_inp  = g_inp[nidx];
            ct_next = g_ct [nidx];
            if (tid == 0) {
                unsigned target = (unsigned)(t + 1) * RP;
                while (*(volatile unsigned*)&g_bar < target) { }   // pure spin
                __threadfence();
            }
            __syncwarp();
            gate = fsigmoid(pf_gl);        // off the serial tail
        }
        __syncthreads();   // syncA: barrier passed, blend[t] visible

        // 2) per-warp self-stage: this warp's 2KB slice (4 batches x 128 floats)
        {
            const float4* src = (const float4*)(g_blend + (t & 1)*BD);
#pragma unroll
            for (int i = 0; i < 4; i++) {
                float4 vv = __ldcg(src + (size_t)i*(DD/4) + w*32 + lane);
                *(float4*)&bl_sw[w][i][lane*4] = vv;
            }
            __syncwarp();
        }

        // 3) register-A GEMV over this warp's k-chunk (packed f32x2)
        {
            const ulonglong2* xb = (const ulonglong2*)&bl_sw[w][bo][0];
            ull s0 = 0ull, s1 = 0ull;
#pragma unroll
            for (int i = 0; i < 32; i++) {
                ulonglong2 x = xb[i];
                ffma2(s0, a2[2*i],   x.x);
                ffma2(s1, a2[2*i+1], x.y);
            }
            float2 p0 = unpack2(s0), p1 = unpack2(s1);
            part[w][lane] = (p0.x + p0.y) + (p1.x + p1.y);
        }
        __syncthreads();   // syncC: partials ready

        // 4) warp 0: reduce + tanh + commit state (no trailing sync)
        if (tid < 32) {
            float s = ct_cur;
#pragma unroll
            for (int ww = 0; ww < 8; ww++) s += part[ww][tid];
            state = ftanh(s);
            __stcg(&g_st[idx0 + (size_t)t*DD], state);
            ct_cur = ct_next;
        }
    }
}

// ------------------------- launch -------------------------------------------
extern "C" void kernel_launch(void* const* d_in, const int* in_sizes, int n_in,
                              void* d_out, int out_size)
{
    const float* q     = (const float*)d_in[0];
    const float* k     = (const float*)d_in[1];
    const float* v     = (const float*)d_in[2];
    const float* Wi    = (const float*)d_in[3];
    const float* bi    = (const float*)d_in[4];
    const float* Wg    = (const float*)d_in[5];
    const float* bg    = (const float*)d_in[6];
    const float* A     = (const float*)d_in[7];
    const float* Bm    = (const float*)d_in[8];
    const float* Wo    = (const float*)d_in[9];
    const float* bo    = (const float*)d_in[10];
    const float* decay = (const float*)d_in[11];
    float* out = (float*)d_out;

    void *p_ret, *p_inp, *p_gl, *p_ct, *p_st;
    cudaGetSymbolAddress(&p_ret, g_ret);
    cudaGetSymbolAddress(&p_inp, g_inp);
    cudaGetSymbolAddress(&p_gl,  g_gl);
    cudaGetSymbolAddress(&p_ct,  g_ct);
    cudaGetSymbolAddress(&p_st,  g_st);

    // launch 1..3: scans (k_reset fused into k_scan1)
    k_scan1<<<(BD*NC)/256, 256>>>(k, v, decay);
    k_scan2<<<BD/256, 256>>>(decay);
    k_scan3<<<(BD*NC)/256, 256>>>(q, k, v, decay);

    dim3 gg(DD/128, MT/128);   // (N tiles, M tiles)
    // launch 4: gemm1 — now in the ncu capture slot
    k_gemm<<<gg, 256>>>((const float*)p_ret, Wi, bi, (float*)p_inp, MT, DD, DD, 1);
    k_gemm<<<gg, 256>>>((const float*)p_inp, Wg, bg, (float*)p_gl, MT, DD, DD, 1);
    k_gemm<<<gg, 256>>>((const float*)p_inp, Bm, (const float*)0, (float*)p_ct, MT, DD, DD, 0);

    k_recur<<<RP, 256>>>(A);

    k_gemm<<<gg, 256>>>((const float*)p_st, Wo, bo, out, MT, DD, DD, 1);
}

// round 13
// speedup vs baseline: 3.0478x; 1.0585x over previous
#include <cuda_runtime.h>
#include <math.h>

#define BB 4
#define SS 2048
#define DD 1024
#define BD (BB*DD)          // 4096
#define MT (BB*SS)          // 8192
#define CH 128
#define NC (SS/CH)          // 16

#define RP   128            // persistent CTAs in recurrence
#define RR   (DD/RP)        // 8 rows per CTA

typedef unsigned long long ull;

// ------------------------- scratch (device globals; no allocation) ---------
__device__ float g_ret[(size_t)MT*DD];
__device__ float g_inp[(size_t)MT*DD];
__device__ float g_gl [(size_t)MT*DD];
__device__ float g_ct [(size_t)MT*DD];
__device__ float g_st [(size_t)MT*DD];
__device__ float g_chend[BD*NC];
__device__ float g_carry[BD*NC];
__device__ float g_blend[2*BD];
__device__ unsigned g_bar;

// ------------------------- helpers ------------------------------------------
__device__ __forceinline__ void cp_async16(unsigned dst, const void* src) {
    asm volatile("cp.async.cg.shared.global [%0], [%1], 16;" :: "r"(dst), "l"(src));
}
#define CP_COMMIT() asm volatile("cp.async.commit_group;")
#define CP_WAIT1()  asm volatile("cp.async.wait_group 1;")
#define CP_WAIT0()  asm volatile("cp.async.wait_group 0;")

__device__ __forceinline__ unsigned f2tf32(float x) {
    unsigned u; asm("cvt.rna.tf32.f32 %0, %1;" : "=r"(u) : "f"(x)); return u;
}
__device__ __forceinline__ void mma_tf32(float* c, const unsigned* a, const unsigned* b) {
    asm volatile(
        "mma.sync.aligned.m16n8k8.row.col.f32.tf32.tf32.f32 "
        "{%0,%1,%2,%3}, {%4,%5,%6,%7}, {%8,%9}, {%0,%1,%2,%3};"
        : "+f"(c[0]), "+f"(c[1]), "+f"(c[2]), "+f"(c[3])
        : "r"(a[0]), "r"(a[1]), "r"(a[2]), "r"(a[3]), "r"(b[0]), "r"(b[1]));
}
__device__ __forceinline__ void ffma2(ull& d, ull a, ull b) {
    asm volatile("fma.rn.f32x2 %0, %1, %2, %0;" : "+l"(d) : "l"(a), "l"(b));
}
__device__ __forceinline__ float2 unpack2(ull v) {
    float2 f; asm("mov.b64 {%0, %1}, %2;" : "=f"(f.x), "=f"(f.y) : "l"(v)); return f;
}
__device__ __forceinline__ float fsigmoid(float x) {
    return __fdividef(1.f, 1.f + __expf(-x));
}
__device__ __forceinline__ float ftanh(float x) {
    x = fminf(fmaxf(x, -15.f), 15.f);
    float e = __expf(2.f * x);
    return __fdividef(e - 1.f, e + 1.f);
}
// release-arrival: orders this thread's prior stores, no full MEMBAR needed
__device__ __forceinline__ void red_release_add(unsigned* p, unsigned v) {
    asm volatile("red.release.gpu.global.add.u32 [%0], %1;" :: "l"(p), "r"(v) : "memory");
}

// ------------------------- retention scan (chunked parallel scan) ----------
// g_bar reset fused here (keeps gemm1 in the ncu capture slot).
__global__ void k_scan1(const float* __restrict__ k, const float* __restrict__ v,
                        const float* __restrict__ decay)
{
    if (blockIdx.x == 0 && threadIdx.x == 0) g_bar = 0u;
    int g = blockIdx.x * blockDim.x + threadIdx.x;
    int d    = g & (DD-1);
    int rest = g >> 10;
    int ch   = rest & (NC-1);
    int b    = rest >> 4;
    float dec = decay[d >> 6];
    size_t base = ((size_t)(b*SS + ch*CH))*DD + d;
    float r = 0.f;
#pragma unroll 4
    for (int t = 0; t < CH; t++) {
        r = dec*r + k[base + (size_t)t*DD] * v[base + (size_t)t*DD];
    }
    g_chend[(b*NC + ch)*DD + d] = r;
}

__global__ void k_scan2(const float* __restrict__ decay)
{
    int g = blockIdx.x * blockDim.x + threadIdx.x;
    int d = g & (DD-1);
    int b = g >> 10;
    float dec = decay[d >> 6];
    float dL = dec;
#pragma unroll
    for (int i = 0; i < 7; i++) dL *= dL;   // dec^128
    float r = 0.f;
#pragma unroll
    for (int ch = 0; ch < NC; ch++) {
        g_carry[(b*NC + ch)*DD + d] = r;
        r = g_chend[(b*NC + ch)*DD + d] + dL * r;
    }
}

__global__ void k_scan3(const float* __restrict__ q, const float* __restrict__ k,
                        const float* __restrict__ v, const float* __restrict__ decay)
{
    int g = blockIdx.x * blockDim.x + threadIdx.x;
    int d    = g & (DD-1);
    int rest = g >> 10;
    int ch   = rest & (NC-1);
    int b    = rest >> 4;
    float dec = decay[d >> 6];
    float r = g_carry[(b*NC + ch)*DD + d];
    size_t base = ((size_t)(b*SS + ch*CH))*DD + d;
#pragma unroll 4
    for (int t = 0; t < CH; t++) {
        size_t o = base + (size_t)t*DD;
        r = dec*r + k[o]*v[o];
        g_ret[o] = q[o]*r;
    }
}

// ------------------------- TF32-split tensor-core GEMM ----------------------
// R4 kernel + __launch_bounds__(256, 2): regs 129 -> 128 so TWO CTAs fit per
// SM (occ 12.5% -> 25%, issue was 35.5% with one CTA).
#define GBK  16
#define GSTR 20

__global__ __launch_bounds__(256, 2)
void k_gemm(const float* __restrict__ Act, const float* __restrict__ W,
            const float* __restrict__ bias, float* __restrict__ C,
            int M, int N, int K, int hasBias)
{
    __shared__ float As[2][128*GSTR];
    __shared__ float Bs[2][128*GSTR];
    int tid  = threadIdx.x;
    int wid  = tid >> 5;
    int lane = tid & 31;
    int g    = lane >> 2;
    int tig  = lane & 3;
    int wm   = wid & 3;
    int wn   = wid >> 2;

    const float* Ab = Act + (size_t)blockIdx.y * 128 * K;
    const float* Wb = W   + (size_t)blockIdx.x * 128 * K;
    unsigned sA0 = (unsigned)__cvta_generic_to_shared(&As[0][0]);
    unsigned sB0 = (unsigned)__cvta_generic_to_shared(&Bs[0][0]);

    float acc[2][8][4];
#pragma unroll
    for (int mt = 0; mt < 2; mt++)
#pragma unroll
        for (int nt = 0; nt < 8; nt++)
#pragma unroll
            for (int i = 0; i < 4; i++) acc[mt][nt][i] = 0.f;

    auto loadTile = [&](int buf, int k0) {
        int f = tid * 2;
#pragma unroll
        for (int i2 = 0; i2 < 2; i2++) {
            int ff  = f + i2;
            int row = ff >> 2;
            int c4  = (ff & 3) * 4;
            cp_async16(sA0 + (unsigned)(buf*128*GSTR + row*GSTR + c4)*4u,
                       Ab + (size_t)row*K + k0 + c4);
            cp_async16(sB0 + (unsigned)(buf*128*GSTR + row*GSTR + c4)*4u,
                       Wb + (size_t)row*K + k0 + c4);
        }
    };

    int nk = K / GBK;
    loadTile(0, 0);
    CP_COMMIT();

    for (int kt = 0; kt < nk; kt++) {
        if (kt + 1 < nk) { loadTile((kt+1) & 1, (kt+1)*GBK); CP_COMMIT(); CP_WAIT1(); }
        else             { CP_WAIT0(); }
        __syncthreads();

        const float* Abs = &As[kt & 1][0];
        const float* Bbs = &Bs[kt & 1][0];
#pragma unroll
        for (int ks = 0; ks < GBK/8; ks++) {
            int kb = ks*8;
            unsigned ah[2][4], al[2][4];
#pragma unroll
            for (int mt = 0; mt < 2; mt++) {
                int rb = wm*32 + mt*16;
                float f0 = Abs[(rb + g    )*GSTR + kb + tig    ];
                float f1 = Abs[(rb + g + 8)*GSTR + kb + tig    ];
                float f2 = Abs[(rb + g    )*GSTR + kb + tig + 4];
                float f3 = Abs[(rb + g + 8)*GSTR + kb + tig + 4];
                ah[mt][0] = f2tf32(f0); al[mt][0] = f2tf32(f0 - __uint_as_float(ah[mt][0]));
                ah[mt][1] = f2tf32(f1); al[mt][1] = f2tf32(f1 - __uint_as_float(ah[mt][1]));
                ah[mt][2] = f2tf32(f2); al[mt][2] = f2tf32(f2 - __uint_as_float(ah[mt][2]));
                ah[mt][3] = f2tf32(f3); al[mt][3] = f2tf32(f3 - __uint_as_float(ah[mt][3]));
            }
            unsigned bh[8][2], bl[8][2];
#pragma unroll
            for (int nt = 0; nt < 8; nt++) {
                int nb = wn*64 + nt*8;
                float f0 = Bbs[(nb + g)*GSTR + kb + tig    ];
                float f1 = Bbs[(nb + g)*GSTR + kb + tig + 4];
                bh[nt][0] = f2tf32(f0); bl[nt][0] = f2tf32(f0 - __uint_as_float(bh[nt][0]));
                bh[nt][1] = f2tf32(f1); bl[nt][1] = f2tf32(f1 - __uint_as_float(bh[nt][1]));
            }
#pragma unroll
            for (int mt = 0; mt < 2; mt++)
#pragma unroll
                for (int nt = 0; nt < 8; nt++) {
                    mma_tf32(acc[mt][nt], ah[mt], bh[nt]);
                    mma_tf32(acc[mt][nt], ah[mt], bl[nt]);
                    mma_tf32(acc[mt][nt], al[mt], bh[nt]);
                }
        }
        __syncthreads();
    }

#pragma unroll
    for (int mt = 0; mt < 2; mt++) {
        int r0 = blockIdx.y*128 + wm*32 + mt*16 + g;
#pragma unroll
        for (int nt = 0; nt < 8; nt++) {
            int c0 = blockIdx.x*128 + wn*64 + nt*8 + 2*tig;
            float b0 = hasBias ? bias[c0]     : 0.f;
            float b1 = hasBias ? bias[c0 + 1] : 0.f;
            float2 o0 = make_float2(acc[mt][nt][0] + b0, acc[mt][nt][1] + b1);
            float2 o1 = make_float2(acc[mt][nt][2] + b0, acc[mt][nt][3] + b1);
            *(float2*)(C + (size_t)r0      *N + c0) = o0;
            *(float2*)(C + (size_t)(r0 + 8)*N + c0) = o1;
        }
    }
}

// ------------------------- sequential state recurrence ----------------------
// R9 structure + TWO-STEP-AHEAD prefetch (use(t) / ready(t+1) / in-flight(t+2)
// register rotation, rotated in phase 4 => DRAM latency AND its variance are
// off the max-of-128 critical chain) + red.release arrival (no full MEMBAR).
__global__ __launch_bounds__(256, 1)
void k_recur(const float* __restrict__ Amat)
{
    __shared__ float bl_sw[8][4][132];   // per-warp slice: [warp][batch][128+pad]
    __shared__ float part[8][32];

    int tid  = threadIdx.x;
    int cta  = blockIdx.x;
    int row0 = cta * RR;
    int w    = tid >> 5;              // warp = k-chunk of 128
    int lane = tid & 31;
    int lr   = lane >> 2;             // local row 0..7
    int bo   = lane & 3;              // batch 0..3

    // A slice in registers, k-pair packed: A[row0+lr][w*128 .. +127]
    ull a2[64];
    {
        const ulonglong2* Ar =
            (const ulonglong2*)(Amat + (size_t)(row0 + lr)*DD + w*128);
#pragma unroll
        for (int i = 0; i < 32; i++) {
            ulonglong2 u = Ar[i];
            a2[2*i]   = u.x;
            a2[2*i+1] = u.y;
        }
    }

    int b2 = tid & 3, l2 = tid >> 2;          // meaningful for tid<32
    size_t idx0 = ((size_t)b2*SS)*DD + row0 + l2;
    float state = 0.f, gate = 0.f;
    float inp_use = 0.f, ct_use = 0.f;        // step t   (ready)
    float gl_nxt = 0.f, inp_nxt = 0.f, ct_nxt = 0.f;   // step t+1 (ready)
    if (tid < 32) {
        float gl0 = g_gl[idx0];
        inp_use = g_inp[idx0];
        ct_use  = g_ct [idx0];
        gl_nxt  = g_gl [idx0 + DD];
        inp_nxt = g_inp[idx0 + DD];
        ct_nxt  = g_ct [idx0 + DD];
        gate    = fsigmoid(gl0);
    }
    __syncthreads();

    for (int t = 0; t < SS; t++) {
        float gl_new = 0.f, inp_new = 0.f, ct_new = 0.f;   // step t+2 (issue now)
        // 1) warp 0: blend + publish + release-arrive; issue t+2 loads; spin-poll
        if (tid < 32) {
            float bl = fmaf(gate, state - inp_use, inp_use);
            __stcg(&g_blend[(t & 1)*BD + b2*DD + row0 + l2], bl);
            __syncwarp();
            if (tid == 0) red_release_add(&g_bar, 1u);
            int t2 = (t + 2 < SS) ? t + 2 : SS - 1;
            size_t nidx = idx0 + (size_t)t2*DD;
            gl_new  = g_gl [nidx];
            inp_new = g_inp[nidx];
            ct_new  = g_ct [nidx];
            if (tid == 0) {
                unsigned target = (unsigned)(t + 1) * RP;
                while (*(volatile unsigned*)&g_bar < target) { }   // pure spin
                __threadfence();                                   // acquire half
            }
            __syncwarp();
        }
        __syncthreads();   // syncA: barrier passed, blend[t] visible

        // 2) per-warp self-stage: this warp's 2KB slice (4 batches x 128 floats)
        {
            const float4* src = (const float4*)(g_blend + (t & 1)*BD);
#pragma unroll
            for (int i = 0; i < 4; i++) {
                float4 vv = __ldcg(src + (size_t)i*(DD/4) + w*32 + lane);
                *(float4*)&bl_sw[w][i][lane*4] = vv;
            }
            __syncwarp();
        }

        // 3) register-A GEMV over this warp's k-chunk (packed f32x2)
        {
            const ulonglong2* xb = (const ulonglong2*)&bl_sw[w][bo][0];
            ull s0 = 0ull, s1 = 0ull;
#pragma unroll
            for (int i = 0; i < 32; i++) {
                ulonglong2 x = xb[i];
                ffma2(s0, a2[2*i],   x.x);
                ffma2(s1, a2[2*i+1], x.y);
            }
            float2 p0 = unpack2(s0), p1 = unpack2(s1);
            part[w][lane] = (p0.x + p0.y) + (p1.x + p1.y);
        }
        __syncthreads();   // syncC: partials ready

        // 4) warp 0: reduce + tanh + commit; rotate prefetch generations
        //    (t+2 loads have had ~a full step to land; no DRAM on the chain)
        if (tid < 32) {
            float s = ct_use;
#pragma unroll
            for (int ww = 0; ww < 8; ww++) s += part[ww][tid];
            state = ftanh(s);
            __stcg(&g_st[idx0 + (size_t)t*DD], state);
            gate    = fsigmoid(gl_nxt);      // for step t+1
            inp_use = inp_nxt;
            ct_use  = ct_nxt;
            gl_nxt  = gl_new;
            inp_nxt = inp_new;
            ct_nxt  = ct_new;
        }
    }
}

// ------------------------- launch -------------------------------------------
extern "C" void kernel_launch(void* const* d_in, const int* in_sizes, int n_in,
                              void* d_out, int out_size)
{
    const float* q     = (const float*)d_in[0];
    const float* k     = (const float*)d_in[1];
    const float* v     = (const float*)d_in[2];
    const float* Wi    = (const float*)d_in[3];
    const float* bi    = (const float*)d_in[4];
    const float* Wg    = (const float*)d_in[5];
    const float* bg    = (const float*)d_in[6];
    const float* A     = (const float*)d_in[7];
    const float* Bm    = (const float*)d_in[8];
    const float* Wo    = (const float*)d_in[9];
    const float* bo    = (const float*)d_in[10];
    const float* decay = (const float*)d_in[11];
    float* out = (float*)d_out;

    void *p_ret, *p_inp, *p_gl, *p_ct, *p_st;
    cudaGetSymbolAddress(&p_ret, g_ret);
    cudaGetSymbolAddress(&p_inp, g_inp);
    cudaGetSymbolAddress(&p_gl,  g_gl);
    cudaGetSymbolAddress(&p_ct,  g_ct);
    cudaGetSymbolAddress(&p_st,  g_st);

    // launches 1..3: scans (g_bar reset fused into k_scan1)
    k_scan1<<<(BD*NC)/256, 256>>>(k, v, decay);
    k_scan2<<<BD/256, 256>>>(decay);
    k_scan3<<<(BD*NC)/256, 256>>>(q, k, v, decay);

    dim3 gg(DD/128, MT/128);   // (N tiles, M tiles)
    // launch 4: gemm1 — ncu capture slot (verifies the occupancy fix)
    k_gemm<<<gg, 256>>>((const float*)p_ret, Wi, bi, (float*)p_inp, MT, DD, DD, 1);
    k_gemm<<<gg, 256>>>((const float*)p_inp, Wg, bg, (float*)p_gl, MT, DD, DD, 1);
    k_gemm<<<gg, 256>>>((const float*)p_inp, Bm, (const float*)0, (float*)p_ct, MT, DD, DD, 0);

    k_recur<<<RP, 256>>>(A);

    k_gemm<<<gg, 256>>>((const float*)p_st, Wo, bo, out, MT, DD, DD, 1);
}

// round 14
// speedup vs baseline: 3.4608x; 1.1355x over previous
#include <cuda_runtime.h>
#include <math.h>

#define BB 4
#define SS 2048
#define DD 1024
#define BD (BB*DD)          // 4096
#define MT (BB*SS)          // 8192
#define CH 128
#define NC (SS/CH)          // 16

#define RPB 32              // CTAs per batch group (4 groups x 32 = 128 CTAs)
#define RROW 32             // rows per CTA (32 CTAs x 32 rows = 1024)

typedef unsigned long long ull;

// ------------------------- scratch (device globals; no allocation) ---------
__device__ float g_ret[(size_t)MT*DD];
__device__ float g_inp[(size_t)MT*DD];
__device__ float g_gl [(size_t)MT*DD];
__device__ float g_ct [(size_t)MT*DD];
__device__ float g_st [(size_t)MT*DD];
__device__ float g_chend[BD*NC];
__device__ float g_carry[BD*NC];
__device__ float g_blend[BB*2*DD];          // per batch: 2 buffers x 1024
__device__ unsigned g_bar4[BB*32];          // 4 counters, 128B apart

// ------------------------- helpers ------------------------------------------
__device__ __forceinline__ void cp_async16(unsigned dst, const void* src) {
    asm volatile("cp.async.cg.shared.global [%0], [%1], 16;" :: "r"(dst), "l"(src));
}
#define CP_COMMIT() asm volatile("cp.async.commit_group;")
#define CP_WAIT1()  asm volatile("cp.async.wait_group 1;")
#define CP_WAIT0()  asm volatile("cp.async.wait_group 0;")

__device__ __forceinline__ unsigned f2tf32(float x) {
    unsigned u; asm("cvt.rna.tf32.f32 %0, %1;" : "=r"(u) : "f"(x)); return u;
}
__device__ __forceinline__ void mma_tf32(float* c, const unsigned* a, const unsigned* b) {
    asm volatile(
        "mma.sync.aligned.m16n8k8.row.col.f32.tf32.tf32.f32 "
        "{%0,%1,%2,%3}, {%4,%5,%6,%7}, {%8,%9}, {%0,%1,%2,%3};"
        : "+f"(c[0]), "+f"(c[1]), "+f"(c[2]), "+f"(c[3])
        : "r"(a[0]), "r"(a[1]), "r"(a[2]), "r"(a[3]), "r"(b[0]), "r"(b[1]));
}
__device__ __forceinline__ void ffma2(ull& d, ull a, ull b) {
    asm volatile("fma.rn.f32x2 %0, %1, %2, %0;" : "+l"(d) : "l"(a), "l"(b));
}
__device__ __forceinline__ float2 unpack2(ull v) {
    float2 f; asm("mov.b64 {%0, %1}, %2;" : "=f"(f.x), "=f"(f.y) : "l"(v)); return f;
}
__device__ __forceinline__ float fsigmoid(float x) {
    return __fdividef(1.f, 1.f + __expf(-x));
}
__device__ __forceinline__ float ftanh(float x) {
    x = fminf(fmaxf(x, -15.f), 15.f);
    float e = __expf(2.f * x);
    return __fdividef(e - 1.f, e + 1.f);
}
__device__ __forceinline__ void red_release_add(unsigned* p, unsigned v) {
    asm volatile("red.release.gpu.global.add.u32 [%0], %1;" :: "l"(p), "r"(v) : "memory");
}

// ------------------------- retention scan (chunked parallel scan) ----------
// barrier-counter reset fused here (keeps gemm1 in the ncu capture slot).
__global__ void k_scan1(const float* __restrict__ k, const float* __restrict__ v,
                        const float* __restrict__ decay)
{
    if (blockIdx.x == 0 && threadIdx.x < BB*32) g_bar4[threadIdx.x] = 0u;
    int g = blockIdx.x * blockDim.x + threadIdx.x;
    int d    = g & (DD-1);
    int rest = g >> 10;
    int ch   = rest & (NC-1);
    int b    = rest >> 4;
    float dec = decay[d >> 6];
    size_t base = ((size_t)(b*SS + ch*CH))*DD + d;
    float r = 0.f;
#pragma unroll 4
    for (int t = 0; t < CH; t++) {
        r = dec*r + k[base + (size_t)t*DD] * v[base + (size_t)t*DD];
    }
    g_chend[(b*NC + ch)*DD + d] = r;
}

__global__ void k_scan2(const float* __restrict__ decay)
{
    int g = blockIdx.x * blockDim.x + threadIdx.x;
    int d = g & (DD-1);
    int b = g >> 10;
    float dec = decay[d >> 6];
    float dL = dec;
#pragma unroll
    for (int i = 0; i < 7; i++) dL *= dL;   // dec^128
    float r = 0.f;
#pragma unroll
    for (int ch = 0; ch < NC; ch++) {
        g_carry[(b*NC + ch)*DD + d] = r;
        r = g_chend[(b*NC + ch)*DD + d] + dL * r;
    }
}

__global__ void k_scan3(const float* __restrict__ q, const float* __restrict__ k,
                        const float* __restrict__ v, const float* __restrict__ decay)
{
    int g = blockIdx.x * blockDim.x + threadIdx.x;
    int d    = g & (DD-1);
    int rest = g >> 10;
    int ch   = rest & (NC-1);
    int b    = rest >> 4;
    float dec = decay[d >> 6];
    float r = g_carry[(b*NC + ch)*DD + d];
    size_t base = ((size_t)(b*SS + ch*CH))*DD + d;
#pragma unroll 4
    for (int t = 0; t < CH; t++) {
        size_t o = base + (size_t)t*DD;
        r = dec*r + k[o]*v[o];
        g_ret[o] = q[o]*r;
    }
}

// ------------------------- TF32-split tensor-core GEMM (frozen, R12) --------
#define GBK  16
#define GSTR 20

__global__ __launch_bounds__(256, 2)
void k_gemm(const float* __restrict__ Act, const float* __restrict__ W,
            const float* __restrict__ bias, float* __restrict__ C,
            int M, int N, int K, int hasBias)
{
    __shared__ float As[2][128*GSTR];
    __shared__ float Bs[2][128*GSTR];
    int tid  = threadIdx.x;
    int wid  = tid >> 5;
    int lane = tid & 31;
    int g    = lane >> 2;
    int tig  = lane & 3;
    int wm   = wid & 3;
    int wn   = wid >> 2;

    const float* Ab = Act + (size_t)blockIdx.y * 128 * K;
    const float* Wb = W   + (size_t)blockIdx.x * 128 * K;
    unsigned sA0 = (unsigned)__cvta_generic_to_shared(&As[0][0]);
    unsigned sB0 = (unsigned)__cvta_generic_to_shared(&Bs[0][0]);

    float acc[2][8][4];
#pragma unroll
    for (int mt = 0; mt < 2; mt++)
#pragma unroll
        for (int nt = 0; nt < 8; nt++)
#pragma unroll
            for (int i = 0; i < 4; i++) acc[mt][nt][i] = 0.f;

    auto loadTile = [&](int buf, int k0) {
        int f = tid * 2;
#pragma unroll
        for (int i2 = 0; i2 < 2; i2++) {
            int ff  = f + i2;
            int row = ff >> 2;
            int c4  = (ff & 3) * 4;
            cp_async16(sA0 + (unsigned)(buf*128*GSTR + row*GSTR + c4)*4u,
                       Ab + (size_t)row*K + k0 + c4);
            cp_async16(sB0 + (unsigned)(buf*128*GSTR + row*GSTR + c4)*4u,
                       Wb + (size_t)row*K + k0 + c4);
        }
    };

    int nk = K / GBK;
    loadTile(0, 0);
    CP_COMMIT();

    for (int kt = 0; kt < nk; kt++) {
        if (kt + 1 < nk) { loadTile((kt+1) & 1, (kt+1)*GBK); CP_COMMIT(); CP_WAIT1(); }
        else             { CP_WAIT0(); }
        __syncthreads();

        const float* Abs = &As[kt & 1][0];
        const float* Bbs = &Bs[kt & 1][0];
#pragma unroll
        for (int ks = 0; ks < GBK/8; ks++) {
            int kb = ks*8;
            unsigned ah[2][4], al[2][4];
#pragma unroll
            for (int mt = 0; mt < 2; mt++) {
                int rb = wm*32 + mt*16;
                float f0 = Abs[(rb + g    )*GSTR + kb + tig    ];
                float f1 = Abs[(rb + g + 8)*GSTR + kb + tig    ];
                float f2 = Abs[(rb + g    )*GSTR + kb + tig + 4];
                float f3 = Abs[(rb + g + 8)*GSTR + kb + tig + 4];
                ah[mt][0] = f2tf32(f0); al[mt][0] = f2tf32(f0 - __uint_as_float(ah[mt][0]));
                ah[mt][1] = f2tf32(f1); al[mt][1] = f2tf32(f1 - __uint_as_float(ah[mt][1]));
                ah[mt][2] = f2tf32(f2); al[mt][2] = f2tf32(f2 - __uint_as_float(ah[mt][2]));
                ah[mt][3] = f2tf32(f3); al[mt][3] = f2tf32(f3 - __uint_as_float(ah[mt][3]));
            }
            unsigned bh[8][2], bl[8][2];
#pragma unroll
            for (int nt = 0; nt < 8; nt++) {
                int nb = wn*64 + nt*8;
                float f0 = Bbs[(nb + g)*GSTR + kb + tig    ];
                float f1 = Bbs[(nb + g)*GSTR + kb + tig + 4];
                bh[nt][0] = f2tf32(f0); bl[nt][0] = f2tf32(f0 - __uint_as_float(bh[nt][0]));
                bh[nt][1] = f2tf32(f1); bl[nt][1] = f2tf32(f1 - __uint_as_float(bh[nt][1]));
            }
#pragma unroll
            for (int mt = 0; mt < 2; mt++)
#pragma unroll
                for (int nt = 0; nt < 8; nt++) {
                    mma_tf32(acc[mt][nt], ah[mt], bh[nt]);
                    mma_tf32(acc[mt][nt], ah[mt], bl[nt]);
                    mma_tf32(acc[mt][nt], al[mt], bh[nt]);
                }
        }
        __syncthreads();
    }

#pragma unroll
    for (int mt = 0; mt < 2; mt++) {
        int r0 = blockIdx.y*128 + wm*32 + mt*16 + g;
#pragma unroll
        for (int nt = 0; nt < 8; nt++) {
            int c0 = blockIdx.x*128 + wn*64 + nt*8 + 2*tig;
            float b0 = hasBias ? bias[c0]     : 0.f;
            float b1 = hasBias ? bias[c0 + 1] : 0.f;
            float2 o0 = make_float2(acc[mt][nt][0] + b0, acc[mt][nt][1] + b1);
            float2 o1 = make_float2(acc[mt][nt][2] + b0, acc[mt][nt][3] + b1);
            *(float2*)(C + (size_t)r0      *N + c0) = o0;
            *(float2*)(C + (size_t)(r0 + 8)*N + c0) = o1;
        }
    }
}

// ------------------------- sequential state recurrence ----------------------
// NEW TOPOLOGY: 4 independent batch groups x 32 CTAs (512 thr, 16 warps).
// CTA (group g, idx c) owns rows [c*32, c*32+32) of batch g's state.
// Warp w owns k-chunk [w*64, w*64+64); lane r owns output row row0+r.
// Per step: warp0 blends+publishes 32 floats (one 128B line) + red.release
// to the GROUP counter (32 arrivals); single poller spins; warps self-stage
// their 64-float x-chunk; 32-FFMA2 GEMV; reduce over 16 warps; tanh.
// Exchange is 4KB/group/step (was 16KB global), barrier is max-of-32.
__global__ __launch_bounds__(512, 1)
void k_recur(const float* __restrict__ Amat)
{
    __shared__ float bl_s[1040];      // x vector (1024) + pad
    __shared__ float part[16][32];

    int tid   = threadIdx.x;
    int cta   = blockIdx.x;           // 0..127
    int batch = cta >> 5;             // 0..3
    int row0  = (cta & 31) * RROW;    // 0..992
    int w     = tid >> 5;             // warp 0..15 = k-chunk of 64
    int lane  = tid & 31;             // lane = output row (row0+lane)

    // A slice: lane r holds A[row0+r][w*64 .. w*64+63] (32 ull, k-pair packed)
    ull a2[32];
    {
        const ulonglong2* Ar =
            (const ulonglong2*)(Amat + (size_t)(row0 + lane)*DD + w*64);
#pragma unroll
        for (int i = 0; i < 16; i++) {
            ulonglong2 u = Ar[i];
            a2[2*i]   = u.x;
            a2[2*i+1] = u.y;
        }
    }

    // per-lane (warp 0) operand streams for rows row0+lane of this batch
    size_t idx0 = ((size_t)batch*SS)*DD + row0 + lane;
    unsigned* bar = &g_bar4[batch*32];
    float* gb0 = &g_blend[(batch*2    )*DD];
    float* gb1 = &g_blend[(batch*2 + 1)*DD];

    float state = 0.f, gate = 0.f;
    float inp_use = 0.f, ct_use = 0.f;               // step t (ready)
    float gl_nxt = 0.f, inp_nxt = 0.f, ct_nxt = 0.f; // step t+1 (ready)
    if (tid < 32) {
        float gl0 = g_gl[idx0];
        inp_use = g_inp[idx0];
        ct_use  = g_ct [idx0];
        gl_nxt  = g_gl [idx0 + DD];
        inp_nxt = g_inp[idx0 + DD];
        ct_nxt  = g_ct [idx0 + DD];
        gate    = fsigmoid(gl0);
    }
    __syncthreads();

    for (int t = 0; t < SS; t++) {
        float* gb = (t & 1) ? gb1 : gb0;
        float gl_new = 0.f, inp_new = 0.f, ct_new = 0.f;   // step t+2 (issue now)

        // 1) warp 0: blend + publish (one 128B line) + release-arrive;
        //    issue t+2 prefetches; spin-poll the group counter.
        if (tid < 32) {
            float bl = fmaf(gate, state - inp_use, inp_use);
            __stcg(&gb[row0 + lane], bl);
            __syncwarp();
            if (lane == 0) red_release_add(bar, 1u);
            int t2 = (t + 2 < SS) ? t + 2 : SS - 1;
            size_t nidx = idx0 + (size_t)t2*DD;
            gl_new  = g_gl [nidx];
            inp_new = g_inp[nidx];
            ct_new  = g_ct [nidx];
            if (lane == 0) {
                unsigned target = (unsigned)(t + 1) * RPB;
                while (*(volatile unsigned*)bar < target) { }   // pure spin
                __threadfence();                                 // acquire half
            }
            __syncwarp();
        }
        __syncthreads();   // syncA: group barrier passed, blend[t] visible

        // 2) per-warp self-stage: this warp's 64-float x-chunk (256B)
        if (lane < 16) {
            float4 vv = __ldcg((const float4*)gb + w*16 + lane);
            *(float4*)&bl_s[w*64 + lane*4] = vv;
        }
        __syncwarp();

        // 3) GEMV: lane r, chunk w -> 32 packed FFMA2 on broadcast x
        {
            const ulonglong2* xb = (const ulonglong2*)&bl_s[w*64];
            ull s0 = 0ull, s1 = 0ull;
#pragma unroll
            for (int i = 0; i < 16; i++) {
                ulonglong2 x = xb[i];
                ffma2(s0, a2[2*i],   x.x);
                ffma2(s1, a2[2*i+1], x.y);
            }
            float2 p0 = unpack2(s0), p1 = unpack2(s1);
            part[w][lane] = (p0.x + p0.y) + (p1.x + p1.y);
        }
        __syncthreads();   // syncC: partials ready

        // 4) warp 0: reduce 16 chunks + tanh + commit; rotate prefetch gens
        if (tid < 32) {
            float s = ct_use;
#pragma unroll
            for (int ww = 0; ww < 16; ww++) s += part[ww][lane];
            state = ftanh(s);
            __stcg(&g_st[idx0 + (size_t)t*DD], state);
            gate    = fsigmoid(gl_nxt);      // for step t+1
            inp_use = inp_nxt;
            ct_use  = ct_nxt;
            gl_nxt  = gl_new;
            inp_nxt = inp_new;
            ct_nxt  = ct_new;
        }
    }
}

// ------------------------- launch -------------------------------------------
extern "C" void kernel_launch(void* const* d_in, const int* in_sizes, int n_in,
                              void* d_out, int out_size)
{
    const float* q     = (const float*)d_in[0];
    const float* k     = (const float*)d_in[1];
    const float* v     = (const float*)d_in[2];
    const float* Wi    = (const float*)d_in[3];
    const float* bi    = (const float*)d_in[4];
    const float* Wg    = (const float*)d_in[5];
    const float* bg    = (const float*)d_in[6];
    const float* A     = (const float*)d_in[7];
    const float* Bm    = (const float*)d_in[8];
    const float* Wo    = (const float*)d_in[9];
    const float* bo    = (const float*)d_in[10];
    const float* decay = (const float*)d_in[11];
    float* out = (float*)d_out;

    void *p_ret, *p_inp, *p_gl, *p_ct, *p_st;
    cudaGetSymbolAddress(&p_ret, g_ret);
    cudaGetSymbolAddress(&p_inp, g_inp);
    cudaGetSymbolAddress(&p_gl,  g_gl);
    cudaGetSymbolAddress(&p_ct,  g_ct);
    cudaGetSymbolAddress(&p_st,  g_st);

    // launches 1..3: scans (counter reset fused into k_scan1)
    k_scan1<<<(BD*NC)/256, 256>>>(k, v, decay);
    k_scan2<<<BD/256, 256>>>(decay);
    k_scan3<<<(BD*NC)/256, 256>>>(q, k, v, decay);

    dim3 gg(DD/128, MT/128);   // (N tiles, M tiles)
    // launch 4: gemm1 — ncu capture slot
    k_gemm<<<gg, 256>>>((const float*)p_ret, Wi, bi, (float*)p_inp, MT, DD, DD, 1);
    k_gemm<<<gg, 256>>>((const float*)p_inp, Wg, bg, (float*)p_gl, MT, DD, DD, 1);
    k_gemm<<<gg, 256>>>((const float*)p_inp, Bm, (const float*)0, (float*)p_ct, MT, DD, DD, 0);

    // sequential recurrence: 4 independent batch groups x 32 CTAs
    k_recur<<<BB*RPB, 512>>>(A);

    k_gemm<<<gg, 256>>>((const float*)p_st, Wo, bo, out, MT, DD, DD, 1);
}